// round 7
// baseline (speedup 1.0000x reference)
#include <cuda_runtime.h>
#include <math.h>

// ---------------------------------------------------------------------------
// mLSTM cell, B=128, D_IN=1024, H=1024  (SIMT; harness ptxas = sm_103 plain,
// tcgen05 unavailable)
// output: concat[ h_new (128*1024), C_new (128*1024*1024), n_new (128*1024) ]
// ---------------------------------------------------------------------------

#define Bsz   128
#define Hdim  1024
#define NQKV  3072   // dead 'g' quarter of proj is skipped
#define KSPLIT 3
#define OUTMN (Bsz * NQKV)   // 393216

__device__ float g_qkv[Bsz * NQKV];        // [b][ q | k | v ]
__device__ float g_ifo[Bsz * NQKV];        // [b][ i | f | o ]
__device__ float g_part[KSPLIT * OUTMN];   // split-K partials (reused K1/K2)
__device__ float g_hpart[8 * Bsz * Hdim];  // per-h-tile h_lin partials
__device__ float g_denom[Bsz];

// ---------------------------------------------------------------------------
// Split-K GEMM mainloop: partial[kz] = A[128, k-chunk] * W[k-chunk, 3072]
// MODE 0: A = x (arg, lda=1024), ldw = 4096 ; MODE 1: A = v slice of g_qkv
// BM=64 BN=128 BK=16, 256 threads, 8x4 per-thread tile, double-buffered smem.
// grid (24, 2, 3) = 144 blocks (~1 wave on 148 SMs); K split 22/21/21 iters.
// ---------------------------------------------------------------------------
template <int MODE>
__global__ __launch_bounds__(256) void gemm_main_kernel(
    const float* __restrict__ Aext, const float* __restrict__ W)
{
    const float* __restrict__ A = (MODE == 0) ? Aext : (const float*)(g_qkv + 2048);
    const int lda = (MODE == 0) ? 1024 : NQKV;
    const int ldw = (MODE == 0) ? 4096 : 3072;

    __shared__ float As[2][16][72];    // [buf][kk][m] transposed, padded
    __shared__ float Bs[2][16][128];   // [buf][kk][n]

    const int tid = threadIdx.x;
    const int bm = blockIdx.y * 64;
    const int bn = blockIdx.x * 128;
    const int kz = blockIdx.z;

    // A loads: 64 rows x 16 k = 256 float4, 1 per thread
    const int aRow = tid >> 2;           // 0..63
    const int aK   = (tid & 3) * 4;
    // B loads: 16 rows(k) x 128 cols = 512 float4, 2 per thread
    const int bRow = tid >> 5;           // 0..7 (and +8)
    const int bCol = (tid & 31) * 4;

    // compute: warp w (=tid>>5) owns M rows w*8..w*8+7 (broadcast from As),
    // lane owns N cols lane*4..+3
    const int mrow = (tid >> 5) * 8;
    const int ncol = (tid & 31) * 4;

    float acc[8][4];
#pragma unroll
    for (int r = 0; r < 8; r++)
#pragma unroll
        for (int c = 0; c < 4; c++) acc[r][c] = 0.f;

    const int it0   = kz * 21 + (kz > 0 ? 1 : 0);   // 0, 22, 43
    const int iters = (kz == 0) ? 22 : 21;

    // ---- prefetch first tile into buffer 0 ----
    {
        const int k0 = it0 * 16;
        float4 av = *(const float4*)(A + (size_t)(bm + aRow) * lda + k0 + aK);
        As[0][aK + 0][aRow] = av.x; As[0][aK + 1][aRow] = av.y;
        As[0][aK + 2][aRow] = av.z; As[0][aK + 3][aRow] = av.w;
        float4 bv0 = *(const float4*)(W + (size_t)(k0 + bRow) * ldw + bn + bCol);
        float4 bv1 = *(const float4*)(W + (size_t)(k0 + bRow + 8) * ldw + bn + bCol);
        *(float4*)&Bs[0][bRow][bCol]     = bv0;
        *(float4*)&Bs[0][bRow + 8][bCol] = bv1;
    }
    __syncthreads();

    int cur = 0;
    for (int it = 0; it < iters; it++) {
        const bool has = (it + 1 < iters);
        float4 av, bv0, bv1;
        if (has) {
            const int k0 = (it0 + it + 1) * 16;
            av  = *(const float4*)(A + (size_t)(bm + aRow) * lda + k0 + aK);
            bv0 = *(const float4*)(W + (size_t)(k0 + bRow) * ldw + bn + bCol);
            bv1 = *(const float4*)(W + (size_t)(k0 + bRow + 8) * ldw + bn + bCol);
        }

#pragma unroll
        for (int kk = 0; kk < 16; kk++) {
            float4 a0 = *(const float4*)&As[cur][kk][mrow];
            float4 a1 = *(const float4*)&As[cur][kk][mrow + 4];
            float4 b4 = *(const float4*)&Bs[cur][kk][ncol];
            float a[8] = {a0.x, a0.y, a0.z, a0.w, a1.x, a1.y, a1.z, a1.w};
            float b[4] = {b4.x, b4.y, b4.z, b4.w};
#pragma unroll
            for (int r = 0; r < 8; r++)
#pragma unroll
                for (int c = 0; c < 4; c++)
                    acc[r][c] = fmaf(a[r], b[c], acc[r][c]);
        }

        if (has) {
            const int nxt = cur ^ 1;
            As[nxt][aK + 0][aRow] = av.x; As[nxt][aK + 1][aRow] = av.y;
            As[nxt][aK + 2][aRow] = av.z; As[nxt][aK + 3][aRow] = av.w;
            *(float4*)&Bs[nxt][bRow][bCol]     = bv0;
            *(float4*)&Bs[nxt][bRow + 8][bCol] = bv1;
            __syncthreads();
            cur = nxt;
        }
    }

    float* __restrict__ part = g_part + (size_t)kz * OUTMN;
#pragma unroll
    for (int r = 0; r < 8; r++) {
        int m = bm + mrow + r;
        float4 o4 = make_float4(acc[r][0], acc[r][1], acc[r][2], acc[r][3]);
        *(float4*)(part + (size_t)m * NQKV + bn + ncol) = o4;
    }
}

// ---------------------------------------------------------------------------
// GEMM epilogue (float4): sum KSPLIT partials + bias + activation
// MODE 0: tanh for n<2048, identity for v ; MODE 1: sigmoid
// 2048 is 4-aligned so the activation region is uniform within a float4.
// ---------------------------------------------------------------------------
template <int MODE>
__global__ __launch_bounds__(256) void gemm_epi_kernel(const float* __restrict__ bias)
{
    const int vi = blockIdx.x * 256 + threadIdx.x;   // 0 .. OUTMN/4-1
    const int idx = vi * 4;
    const int nn = idx % NQKV;

    float4 v = *(const float4*)(bias + nn);
#pragma unroll
    for (int p = 0; p < KSPLIT; p++) {
        float4 pv = *(const float4*)(g_part + (size_t)p * OUTMN + idx);
        v.x += pv.x; v.y += pv.y; v.z += pv.z; v.w += pv.w;
    }
    if (MODE == 0) {
        if (nn < 2048) {
            v.x = tanhf(v.x); v.y = tanhf(v.y);
            v.z = tanhf(v.z); v.w = tanhf(v.w);
        }
        *(float4*)(g_qkv + idx) = v;
    } else {
        v.x = 1.0f / (1.0f + expf(-v.x));
        v.y = 1.0f / (1.0f + expf(-v.y));
        v.z = 1.0f / (1.0f + expf(-v.z));
        v.w = 1.0f / (1.0f + expf(-v.w));
        *(float4*)(g_ifo + idx) = v;
    }
}

// ---------------------------------------------------------------------------
// n_new = f*n + i*k ; denom[b] = max(sum_d q*n_new, 1e-6)
// ---------------------------------------------------------------------------
__global__ __launch_bounds__(256) void nnew_denom_kernel(
    const float* __restrict__ n_in, float* __restrict__ out_n)
{
    const int b = blockIdx.x;
    const int tid = threadIdx.x;
    __shared__ float red[256];

    float psum = 0.f;
#pragma unroll
    for (int d = tid; d < Hdim; d += 256) {
        float iv = g_ifo[b * NQKV + d];
        float fv = g_ifo[b * NQKV + 1024 + d];
        float kv = g_qkv[b * NQKV + 1024 + d];
        float qv = g_qkv[b * NQKV + d];
        float nn = fv * n_in[b * Hdim + d] + iv * kv;
        out_n[b * Hdim + d] = nn;
        psum += qv * nn;
    }
    red[tid] = psum;
    __syncthreads();
#pragma unroll
    for (int s = 128; s > 0; s >>= 1) {
        if (tid < s) red[tid] += red[tid + s];
        __syncthreads();
    }
    if (tid == 0) g_denom[b] = fmaxf(red[0], 1e-6f);
}

// ---------------------------------------------------------------------------
// K3: streaming C update fused with h_lin reduction (single pass over C).
// grid = 128 b * 8 htiles = 1024 blocks, 256 threads (full 1024-wide d row).
// ---------------------------------------------------------------------------
#define TILE_H 128

__global__ __launch_bounds__(256) void update_C_kernel(
    const float* __restrict__ C, float* __restrict__ outC)
{
    const int bid = blockIdx.x;
    const int b  = bid >> 3;
    const int ht = bid & 7;
    const int tid = threadIdx.x;

    __shared__ float qs[TILE_H], fs[TILE_H], iks[TILE_H];
    if (tid < TILE_H) {
        int h = ht * TILE_H + tid;
        qs[tid]  = g_qkv[b * NQKV + h];
        float kv = g_qkv[b * NQKV + 1024 + h];
        float iv = g_ifo[b * NQKV + h];
        fs[tid]  = g_ifo[b * NQKV + 1024 + h];
        iks[tid] = iv * kv;
    }
    __syncthreads();

    const int d = tid * 4;
    const float4 v4 = *(const float4*)(g_qkv + b * NQKV + 2048 + d);

    const size_t base = (size_t)b * Hdim * Hdim + (size_t)ht * TILE_H * Hdim + d;
    const float* __restrict__ src = C + base;
    float* __restrict__ dst = outC + base;

    float4 acc = make_float4(0.f, 0.f, 0.f, 0.f);

#pragma unroll 16
    for (int j = 0; j < TILE_H; j++) {
        float4 c4 = __ldcs((const float4*)(src + (size_t)j * Hdim));
        const float fv = fs[j], ik = iks[j], qv = qs[j];
        float4 cn;
        cn.x = fmaf(fv, c4.x, ik * v4.x);
        cn.y = fmaf(fv, c4.y, ik * v4.y);
        cn.z = fmaf(fv, c4.z, ik * v4.z);
        cn.w = fmaf(fv, c4.w, ik * v4.w);
        __stcs((float4*)(dst + (size_t)j * Hdim), cn);
        acc.x = fmaf(qv, cn.x, acc.x);
        acc.y = fmaf(qv, cn.y, acc.y);
        acc.z = fmaf(qv, cn.z, acc.z);
        acc.w = fmaf(qv, cn.w, acc.w);
    }

    *(float4*)(g_hpart + ht * (Bsz * Hdim) + (b << 10) + d) = acc;
}

// ---------------------------------------------------------------------------
// K4: h_new = o * (sum_ht h_lin_part) / denom
// ---------------------------------------------------------------------------
__global__ __launch_bounds__(256) void finalize_h_kernel(float* __restrict__ out_h)
{
    const int idx = blockIdx.x * 256 + threadIdx.x;   // 131072 total
    const int b = idx >> 10;
    const int d = idx & 1023;
    float hl = 0.f;
#pragma unroll
    for (int p = 0; p < 8; p++) hl += g_hpart[p * (Bsz * Hdim) + (b << 10) + d];
    out_h[idx] = g_ifo[b * NQKV + 2048 + d] * hl / g_denom[b];
}

// ---------------------------------------------------------------------------
extern "C" void kernel_launch(void* const* d_in, const int* in_sizes, int n_in,
                              void* d_out, int out_size)
{
    // order-agnostic input resolution by element count
    const float *x = 0, *C = 0, *n_in_p = 0;
    const float *W_proj = 0, *b_proj = 0, *W_gates = 0, *b_gates = 0;

    const float* trio[3] = {0, 0, 0};
    int ntrio = 0;
    for (int idx = 0; idx < n_in; idx++) {
        const float* p = (const float*)d_in[idx];
        switch (in_sizes[idx]) {
            case 134217728: C       = p; break;
            case 4194304:   W_proj  = p; break;
            case 3145728:   W_gates = p; break;
            case 4096:      b_proj  = p; break;
            case 3072:      b_gates = p; break;
            case 131072:    if (ntrio < 3) trio[ntrio++] = p; break;
            default: break;
        }
    }
    n_in_p = trio[1];
    if (in_sizes[0] == 131072) x = trio[0];
    else                       x = trio[2];

    float* out   = (float*)d_out;
    float* out_h = out;
    float* out_C = out + Bsz * Hdim;
    float* out_n = out + Bsz * Hdim + (size_t)Bsz * Hdim * Hdim;

    dim3 ggrid(NQKV / 128, Bsz / 64, KSPLIT);   // (24, 2, 3) = 144 blocks
    // K1: proj GEMM -> partials -> epi(tanh/identity) -> g_qkv
    gemm_main_kernel<0><<<ggrid, 256>>>(x, W_proj);
    gemm_epi_kernel<0><<<OUTMN / 1024, 256>>>(b_proj);
    // K2: gates GEMM (A = v slice, resolved in-device) -> epi(sigmoid) -> g_ifo
    gemm_main_kernel<1><<<ggrid, 256>>>(nullptr, W_gates);
    gemm_epi_kernel<1><<<OUTMN / 1024, 256>>>(b_gates);
    // n_new + denom
    nnew_denom_kernel<<<Bsz, 256>>>(n_in_p, out_n);
    // C update + fused h_lin reduction (single pass over C)
    update_C_kernel<<<Bsz * 8, 256>>>(C, out_C);
    // finalize h
    finalize_h_kernel<<<(Bsz * Hdim) / 256, 256>>>(out_h);
}

// round 8
// speedup vs baseline: 1.2176x; 1.2176x over previous
#include <cuda_runtime.h>
#include <math.h>

// ---------------------------------------------------------------------------
// mLSTM cell, B=128, D_IN=1024, H=1024  (SIMT; harness ptxas = sm_103 plain,
// tcgen05 unavailable)
// output: concat[ h_new (128*1024), C_new (128*1024*1024), n_new (128*1024) ]
// ---------------------------------------------------------------------------

#define Bsz   128
#define Hdim  1024
#define NQKV  3072   // dead 'g' quarter of proj is skipped
#define KSPLIT 6
#define OUTMN (Bsz * NQKV)   // 393216

__device__ float g_qkv[Bsz * NQKV];        // [b][ q | k | v ]
__device__ float g_ifo[Bsz * NQKV];        // [b][ i | f | o ]
__device__ float g_part[KSPLIT * OUTMN];   // split-K partials (reused K1/K2)
__device__ float g_hpart[8 * Bsz * Hdim];  // per-h-tile h_lin partials
__device__ float g_denom[Bsz];

// ---------------------------------------------------------------------------
// Split-K GEMM mainloop: partial[kz] = A[128, k-chunk] * W[k-chunk, 3072]
// MODE 0: A = x (arg, lda=1024), ldw = 4096 ; MODE 1: A = v slice of g_qkv
// BM=128 BN=128 BK=16, 256 threads, 8x8 per-thread tile, double-buffered.
// grid (24, 1, 6) = 144 blocks (1/SM); K split 11/11/11/11/10/10 BK-iters.
// ---------------------------------------------------------------------------
template <int MODE>
__global__ __launch_bounds__(256) void gemm_main_kernel(
    const float* __restrict__ Aext, const float* __restrict__ W)
{
    const float* __restrict__ A = (MODE == 0) ? Aext : (const float*)(g_qkv + 2048);
    const int lda = (MODE == 0) ? 1024 : NQKV;
    const int ldw = (MODE == 0) ? 4096 : 3072;

    __shared__ float As[2][16][132];   // [buf][kk][m] transposed, padded
    __shared__ float Bs[2][16][128];   // [buf][kk][n]

    const int tid = threadIdx.x;
    const int bn = blockIdx.x * 128;
    const int kz = blockIdx.z;

    // A loads: 128 rows x 16 k = 512 float4, 2 per thread
    const int aRow = tid >> 1;           // 0..127
    const int aK   = (tid & 1) * 8;      // 0 or 8 (two float4: aK, aK+4)
    // B loads: 16 rows(k) x 128 cols = 512 float4, 2 per thread
    const int bRow = tid >> 4;           // 0..15
    const int bCol = (tid & 15) * 8;     // two float4: bCol, bCol+4

    // compute: ty 0..15 -> 8 M rows (ty*8..+7), tx 0..15 -> 8 N cols
    const int mrow = (tid >> 4) * 8;
    const int ncol = (tid & 15) * 8;

    float acc[8][8];
#pragma unroll
    for (int r = 0; r < 8; r++)
#pragma unroll
        for (int c = 0; c < 8; c++) acc[r][c] = 0.f;

    // K split: 64 BK-iters as 11,11,11,11,10,10
    const int it0   = kz * 10 + (kz < 4 ? kz : 4);
    const int iters = (kz < 4) ? 11 : 10;

    // ---- prefetch first tile into buffer 0 ----
    {
        const int k0 = it0 * 16;
        float4 av0 = *(const float4*)(A + (size_t)aRow * lda + k0 + aK);
        float4 av1 = *(const float4*)(A + (size_t)aRow * lda + k0 + aK + 4);
        As[0][aK + 0][aRow] = av0.x; As[0][aK + 1][aRow] = av0.y;
        As[0][aK + 2][aRow] = av0.z; As[0][aK + 3][aRow] = av0.w;
        As[0][aK + 4][aRow] = av1.x; As[0][aK + 5][aRow] = av1.y;
        As[0][aK + 6][aRow] = av1.z; As[0][aK + 7][aRow] = av1.w;
        float4 bv0 = *(const float4*)(W + (size_t)(k0 + bRow) * ldw + bn + bCol);
        float4 bv1 = *(const float4*)(W + (size_t)(k0 + bRow) * ldw + bn + bCol + 4);
        *(float4*)&Bs[0][bRow][bCol]     = bv0;
        *(float4*)&Bs[0][bRow][bCol + 4] = bv1;
    }
    __syncthreads();

    int cur = 0;
    for (int it = 0; it < iters; it++) {
        const bool has = (it + 1 < iters);
        float4 av0, av1, bv0, bv1;
        if (has) {
            const int k0 = (it0 + it + 1) * 16;
            av0 = *(const float4*)(A + (size_t)aRow * lda + k0 + aK);
            av1 = *(const float4*)(A + (size_t)aRow * lda + k0 + aK + 4);
            bv0 = *(const float4*)(W + (size_t)(k0 + bRow) * ldw + bn + bCol);
            bv1 = *(const float4*)(W + (size_t)(k0 + bRow) * ldw + bn + bCol + 4);
        }

#pragma unroll
        for (int kk = 0; kk < 16; kk++) {
            float4 a0 = *(const float4*)&As[cur][kk][mrow];
            float4 a1 = *(const float4*)&As[cur][kk][mrow + 4];
            float4 b0 = *(const float4*)&Bs[cur][kk][ncol];
            float4 b1 = *(const float4*)&Bs[cur][kk][ncol + 4];
            float a[8] = {a0.x, a0.y, a0.z, a0.w, a1.x, a1.y, a1.z, a1.w};
            float b[8] = {b0.x, b0.y, b0.z, b0.w, b1.x, b1.y, b1.z, b1.w};
#pragma unroll
            for (int r = 0; r < 8; r++)
#pragma unroll
                for (int c = 0; c < 8; c++)
                    acc[r][c] = fmaf(a[r], b[c], acc[r][c]);
        }

        if (has) {
            const int nxt = cur ^ 1;
            As[nxt][aK + 0][aRow] = av0.x; As[nxt][aK + 1][aRow] = av0.y;
            As[nxt][aK + 2][aRow] = av0.z; As[nxt][aK + 3][aRow] = av0.w;
            As[nxt][aK + 4][aRow] = av1.x; As[nxt][aK + 5][aRow] = av1.y;
            As[nxt][aK + 6][aRow] = av1.z; As[nxt][aK + 7][aRow] = av1.w;
            *(float4*)&Bs[nxt][bRow][bCol]     = bv0;
            *(float4*)&Bs[nxt][bRow][bCol + 4] = bv1;
            __syncthreads();
            cur = nxt;
        }
    }

    float* __restrict__ part = g_part + (size_t)kz * OUTMN;
#pragma unroll
    for (int r = 0; r < 8; r++) {
        int m = mrow + r;
        *(float4*)(part + (size_t)m * NQKV + bn + ncol) =
            make_float4(acc[r][0], acc[r][1], acc[r][2], acc[r][3]);
        *(float4*)(part + (size_t)m * NQKV + bn + ncol + 4) =
            make_float4(acc[r][4], acc[r][5], acc[r][6], acc[r][7]);
    }
}

// ---------------------------------------------------------------------------
// GEMM epilogue: sum KSPLIT partials + bias + activation -> g_qkv / g_ifo
// MODE 0: tanh for n<2048, identity for v ; MODE 1: sigmoid
// ---------------------------------------------------------------------------
template <int MODE>
__global__ __launch_bounds__(256) void gemm_epi_kernel(const float* __restrict__ bias)
{
    const int idx = blockIdx.x * 256 + threadIdx.x;   // 0 .. OUTMN-1
    const int nn = idx % NQKV;
    float v = bias[nn];
#pragma unroll
    for (int p = 0; p < KSPLIT; p++) v += g_part[(size_t)p * OUTMN + idx];
    if (MODE == 0) {
        if (nn < 2048) v = tanhf(v);
        g_qkv[idx] = v;
    } else {
        g_ifo[idx] = 1.0f / (1.0f + expf(-v));
    }
}

// ---------------------------------------------------------------------------
// n_new = f*n + i*k ; denom[b] = max(sum_d q*n_new, 1e-6)
// ---------------------------------------------------------------------------
__global__ __launch_bounds__(256) void nnew_denom_kernel(
    const float* __restrict__ n_in, float* __restrict__ out_n)
{
    const int b = blockIdx.x;
    const int tid = threadIdx.x;
    __shared__ float red[256];

    float psum = 0.f;
#pragma unroll
    for (int d = tid; d < Hdim; d += 256) {
        float iv = g_ifo[b * NQKV + d];
        float fv = g_ifo[b * NQKV + 1024 + d];
        float kv = g_qkv[b * NQKV + 1024 + d];
        float qv = g_qkv[b * NQKV + d];
        float nn = fv * n_in[b * Hdim + d] + iv * kv;
        out_n[b * Hdim + d] = nn;
        psum += qv * nn;
    }
    red[tid] = psum;
    __syncthreads();
#pragma unroll
    for (int s = 128; s > 0; s >>= 1) {
        if (tid < s) red[tid] += red[tid + s];
        __syncthreads();
    }
    if (tid == 0) g_denom[b] = fmaxf(red[0], 1e-6f);
}

// ---------------------------------------------------------------------------
// K3: streaming C update fused with h_lin reduction (single pass over C).
// grid = 128 b * 8 htiles = 1024 blocks, 256 threads (full 1024-wide d row).
// EXACT round-6 form (unroll 8) — unroll 16 regressed in round 7.
// ---------------------------------------------------------------------------
#define TILE_H 128

__global__ __launch_bounds__(256) void update_C_kernel(
    const float* __restrict__ C, float* __restrict__ outC)
{
    const int bid = blockIdx.x;
    const int b  = bid >> 3;
    const int ht = bid & 7;
    const int tid = threadIdx.x;

    __shared__ float qs[TILE_H], fs[TILE_H], iks[TILE_H];
    if (tid < TILE_H) {
        int h = ht * TILE_H + tid;
        qs[tid]  = g_qkv[b * NQKV + h];
        float kv = g_qkv[b * NQKV + 1024 + h];
        float iv = g_ifo[b * NQKV + h];
        fs[tid]  = g_ifo[b * NQKV + 1024 + h];
        iks[tid] = iv * kv;
    }
    __syncthreads();

    const int d = tid * 4;
    const float4 v4 = *(const float4*)(g_qkv + b * NQKV + 2048 + d);

    const size_t base = (size_t)b * Hdim * Hdim + (size_t)ht * TILE_H * Hdim + d;
    const float* __restrict__ src = C + base;
    float* __restrict__ dst = outC + base;

    float4 acc = make_float4(0.f, 0.f, 0.f, 0.f);

#pragma unroll 8
    for (int j = 0; j < TILE_H; j++) {
        float4 c4 = __ldcs((const float4*)(src + (size_t)j * Hdim));
        const float fv = fs[j], ik = iks[j], qv = qs[j];
        float4 cn;
        cn.x = fmaf(fv, c4.x, ik * v4.x);
        cn.y = fmaf(fv, c4.y, ik * v4.y);
        cn.z = fmaf(fv, c4.z, ik * v4.z);
        cn.w = fmaf(fv, c4.w, ik * v4.w);
        __stcs((float4*)(dst + (size_t)j * Hdim), cn);
        acc.x = fmaf(qv, cn.x, acc.x);
        acc.y = fmaf(qv, cn.y, acc.y);
        acc.z = fmaf(qv, cn.z, acc.z);
        acc.w = fmaf(qv, cn.w, acc.w);
    }

    *(float4*)(g_hpart + ht * (Bsz * Hdim) + (b << 10) + d) = acc;
}

// ---------------------------------------------------------------------------
// K4: h_new = o * (sum_ht h_lin_part) / denom
// ---------------------------------------------------------------------------
__global__ __launch_bounds__(256) void finalize_h_kernel(float* __restrict__ out_h)
{
    const int idx = blockIdx.x * 256 + threadIdx.x;   // 131072 total
    const int b = idx >> 10;
    const int d = idx & 1023;
    float hl = 0.f;
#pragma unroll
    for (int p = 0; p < 8; p++) hl += g_hpart[p * (Bsz * Hdim) + (b << 10) + d];
    out_h[idx] = g_ifo[b * NQKV + 2048 + d] * hl / g_denom[b];
}

// ---------------------------------------------------------------------------
extern "C" void kernel_launch(void* const* d_in, const int* in_sizes, int n_in,
                              void* d_out, int out_size)
{
    // order-agnostic input resolution by element count
    const float *x = 0, *C = 0, *n_in_p = 0;
    const float *W_proj = 0, *b_proj = 0, *W_gates = 0, *b_gates = 0;

    const float* trio[3] = {0, 0, 0};
    int ntrio = 0;
    for (int idx = 0; idx < n_in; idx++) {
        const float* p = (const float*)d_in[idx];
        switch (in_sizes[idx]) {
            case 134217728: C       = p; break;
            case 4194304:   W_proj  = p; break;
            case 3145728:   W_gates = p; break;
            case 4096:      b_proj  = p; break;
            case 3072:      b_gates = p; break;
            case 131072:    if (ntrio < 3) trio[ntrio++] = p; break;
            default: break;
        }
    }
    n_in_p = trio[1];
    if (in_sizes[0] == 131072) x = trio[0];
    else                       x = trio[2];

    float* out   = (float*)d_out;
    float* out_h = out;
    float* out_C = out + Bsz * Hdim;
    float* out_n = out + Bsz * Hdim + (size_t)Bsz * Hdim * Hdim;

    dim3 ggrid(NQKV / 128, 1, KSPLIT);   // (24, 1, 6) = 144 blocks
    // K1: proj GEMM -> partials -> epi(tanh/identity) -> g_qkv
    gemm_main_kernel<0><<<ggrid, 256>>>(x, W_proj);
    gemm_epi_kernel<0><<<OUTMN / 256, 256>>>(b_proj);
    // K2: gates GEMM (A = v slice, resolved in-device) -> epi(sigmoid) -> g_ifo
    gemm_main_kernel<1><<<ggrid, 256>>>(nullptr, W_gates);
    gemm_epi_kernel<1><<<OUTMN / 256, 256>>>(b_gates);
    // n_new + denom
    nnew_denom_kernel<<<Bsz, 256>>>(n_in_p, out_n);
    // C update + fused h_lin reduction (single pass over C)
    update_C_kernel<<<Bsz * 8, 256>>>(C, out_C);
    // finalize h
    finalize_h_kernel<<<(Bsz * Hdim) / 256, 256>>>(out_h);
}

// round 9
// speedup vs baseline: 1.2363x; 1.0153x over previous
#include <cuda_runtime.h>
#include <math.h>
#include <stdint.h>

// ---------------------------------------------------------------------------
// mLSTM cell, B=128, D_IN=1024, H=1024  (SIMT + packed f32x2 FMA;
// harness ptxas = sm_103 plain, tcgen05 unavailable)
// output: concat[ h_new (128*1024), C_new (128*1024*1024), n_new (128*1024) ]
// ---------------------------------------------------------------------------

#define Bsz   128
#define Hdim  1024
#define NQKV  3072   // dead 'g' quarter of proj is skipped
#define KSPLIT 6
#define OUTMN (Bsz * NQKV)   // 393216

__device__ float g_qkv[Bsz * NQKV];        // [b][ q | k | v ]
__device__ float g_ifo[Bsz * NQKV];        // [b][ i | f | o ]
__device__ float g_part[KSPLIT * OUTMN];   // split-K partials (reused K1/K2)
__device__ float g_hpart[8 * Bsz * Hdim];  // per-h-tile h_lin partials
__device__ float g_denom[Bsz];

// packed f32x2 helpers (base sm_100 ISA; plain sm_103 target)
__device__ __forceinline__ unsigned long long pack_dup(float a) {
    unsigned long long r;
    uint32_t au = __float_as_uint(a);
    asm("mov.b64 %0, {%1, %1};" : "=l"(r) : "r"(au));
    return r;
}
__device__ __forceinline__ void fma2(unsigned long long& d,
                                     unsigned long long a,
                                     unsigned long long b) {
    asm("fma.rn.f32x2 %0, %1, %2, %0;" : "+l"(d) : "l"(a), "l"(b));
}
__device__ __forceinline__ float2 unpack2(unsigned long long v) {
    uint32_t lo, hi;
    asm("mov.b64 {%0, %1}, %2;" : "=r"(lo), "=r"(hi) : "l"(v));
    return make_float2(__uint_as_float(lo), __uint_as_float(hi));
}

// ---------------------------------------------------------------------------
// Split-K GEMM mainloop: partial[kz] = A[128, k-chunk] * W[k-chunk, 3072]
// MODE 0: A = x (arg, lda=1024), ldw = 4096 ; MODE 1: A = v slice of g_qkv
// BM=128 BN=128 BK=16, 256 threads, 8x8 per-thread tile via FFMA2 (8x4 pairs),
// double-buffered smem. grid (24, 1, 6) = 144 blocks; K split 11x4 + 10x2.
// ---------------------------------------------------------------------------
template <int MODE>
__global__ __launch_bounds__(256) void gemm_main_kernel(
    const float* __restrict__ Aext, const float* __restrict__ W)
{
    const float* __restrict__ A = (MODE == 0) ? Aext : (const float*)(g_qkv + 2048);
    const int lda = (MODE == 0) ? 1024 : NQKV;
    const int ldw = (MODE == 0) ? 4096 : 3072;

    __shared__ float As[2][16][132];   // [buf][kk][m] transposed, padded
    __shared__ float Bs[2][16][128];   // [buf][kk][n]

    const int tid = threadIdx.x;
    const int bn = blockIdx.x * 128;
    const int kz = blockIdx.z;

    // A loads: 128 rows x 16 k = 512 float4, 2 per thread
    const int aRow = tid >> 1;           // 0..127
    const int aK   = (tid & 1) * 8;      // 0 or 8 (two float4: aK, aK+4)
    // B loads: 16 rows(k) x 128 cols = 512 float4, 2 per thread
    const int bRow = tid >> 4;           // 0..15
    const int bCol = (tid & 15) * 8;     // two float4: bCol, bCol+4

    // compute: ty 0..15 -> 8 M rows (ty*8..+7), tx 0..15 -> 8 N cols (4 pairs)
    const int mrow = (tid >> 4) * 8;
    const int ncol = (tid & 15) * 8;

    unsigned long long acc2[8][4];       // packed (col 2c, 2c+1) fp32 pairs
#pragma unroll
    for (int r = 0; r < 8; r++)
#pragma unroll
        for (int c = 0; c < 4; c++) acc2[r][c] = 0ull;

    // K split: 64 BK-iters as 11,11,11,11,10,10
    const int it0   = kz * 10 + (kz < 4 ? kz : 4);
    const int iters = (kz < 4) ? 11 : 10;

    // ---- prefetch first tile into buffer 0 ----
    {
        const int k0 = it0 * 16;
        float4 av0 = *(const float4*)(A + (size_t)aRow * lda + k0 + aK);
        float4 av1 = *(const float4*)(A + (size_t)aRow * lda + k0 + aK + 4);
        As[0][aK + 0][aRow] = av0.x; As[0][aK + 1][aRow] = av0.y;
        As[0][aK + 2][aRow] = av0.z; As[0][aK + 3][aRow] = av0.w;
        As[0][aK + 4][aRow] = av1.x; As[0][aK + 5][aRow] = av1.y;
        As[0][aK + 6][aRow] = av1.z; As[0][aK + 7][aRow] = av1.w;
        float4 bv0 = *(const float4*)(W + (size_t)(k0 + bRow) * ldw + bn + bCol);
        float4 bv1 = *(const float4*)(W + (size_t)(k0 + bRow) * ldw + bn + bCol + 4);
        *(float4*)&Bs[0][bRow][bCol]     = bv0;
        *(float4*)&Bs[0][bRow][bCol + 4] = bv1;
    }
    __syncthreads();

    int cur = 0;
    for (int it = 0; it < iters; it++) {
        const bool has = (it + 1 < iters);
        float4 av0, av1, bv0, bv1;
        if (has) {
            const int k0 = (it0 + it + 1) * 16;
            av0 = *(const float4*)(A + (size_t)aRow * lda + k0 + aK);
            av1 = *(const float4*)(A + (size_t)aRow * lda + k0 + aK + 4);
            bv0 = *(const float4*)(W + (size_t)(k0 + bRow) * ldw + bn + bCol);
            bv1 = *(const float4*)(W + (size_t)(k0 + bRow) * ldw + bn + bCol + 4);
        }

#pragma unroll
        for (int kk = 0; kk < 16; kk++) {
            float4 a0 = *(const float4*)&As[cur][kk][mrow];
            float4 a1 = *(const float4*)&As[cur][kk][mrow + 4];
            ulonglong2 bb0 = *(const ulonglong2*)&Bs[cur][kk][ncol];      // pairs 0,1
            ulonglong2 bb1 = *(const ulonglong2*)&Bs[cur][kk][ncol + 4];  // pairs 2,3
            unsigned long long a2[8];
            a2[0] = pack_dup(a0.x); a2[1] = pack_dup(a0.y);
            a2[2] = pack_dup(a0.z); a2[3] = pack_dup(a0.w);
            a2[4] = pack_dup(a1.x); a2[5] = pack_dup(a1.y);
            a2[6] = pack_dup(a1.z); a2[7] = pack_dup(a1.w);
#pragma unroll
            for (int r = 0; r < 8; r++) {
                fma2(acc2[r][0], a2[r], bb0.x);
                fma2(acc2[r][1], a2[r], bb0.y);
                fma2(acc2[r][2], a2[r], bb1.x);
                fma2(acc2[r][3], a2[r], bb1.y);
            }
        }

        if (has) {
            const int nxt = cur ^ 1;
            As[nxt][aK + 0][aRow] = av0.x; As[nxt][aK + 1][aRow] = av0.y;
            As[nxt][aK + 2][aRow] = av0.z; As[nxt][aK + 3][aRow] = av0.w;
            As[nxt][aK + 4][aRow] = av1.x; As[nxt][aK + 5][aRow] = av1.y;
            As[nxt][aK + 6][aRow] = av1.z; As[nxt][aK + 7][aRow] = av1.w;
            *(float4*)&Bs[nxt][bRow][bCol]     = bv0;
            *(float4*)&Bs[nxt][bRow][bCol + 4] = bv1;
            __syncthreads();
            cur = nxt;
        }
    }

    float* __restrict__ part = g_part + (size_t)kz * OUTMN;
#pragma unroll
    for (int r = 0; r < 8; r++) {
        int m = mrow + r;
        float2 p0 = unpack2(acc2[r][0]);
        float2 p1 = unpack2(acc2[r][1]);
        float2 p2 = unpack2(acc2[r][2]);
        float2 p3 = unpack2(acc2[r][3]);
        *(float4*)(part + (size_t)m * NQKV + bn + ncol) =
            make_float4(p0.x, p0.y, p1.x, p1.y);
        *(float4*)(part + (size_t)m * NQKV + bn + ncol + 4) =
            make_float4(p2.x, p2.y, p3.x, p3.y);
    }
}

// ---------------------------------------------------------------------------
// GEMM epilogue: sum KSPLIT partials + bias + activation -> g_qkv / g_ifo
// MODE 0: tanh for n<2048, identity for v ; MODE 1: sigmoid
// ---------------------------------------------------------------------------
template <int MODE>
__global__ __launch_bounds__(256) void gemm_epi_kernel(const float* __restrict__ bias)
{
    const int idx = blockIdx.x * 256 + threadIdx.x;   // 0 .. OUTMN-1
    const int nn = idx % NQKV;
    float v = bias[nn];
#pragma unroll
    for (int p = 0; p < KSPLIT; p++) v += g_part[(size_t)p * OUTMN + idx];
    if (MODE == 0) {
        if (nn < 2048) v = tanhf(v);
        g_qkv[idx] = v;
    } else {
        g_ifo[idx] = 1.0f / (1.0f + expf(-v));
    }
}

// ---------------------------------------------------------------------------
// n_new = f*n + i*k ; denom[b] = max(sum_d q*n_new, 1e-6)
// ---------------------------------------------------------------------------
__global__ __launch_bounds__(256) void nnew_denom_kernel(
    const float* __restrict__ n_in, float* __restrict__ out_n)
{
    const int b = blockIdx.x;
    const int tid = threadIdx.x;
    __shared__ float red[256];

    float psum = 0.f;
#pragma unroll
    for (int d = tid; d < Hdim; d += 256) {
        float iv = g_ifo[b * NQKV + d];
        float fv = g_ifo[b * NQKV + 1024 + d];
        float kv = g_qkv[b * NQKV + 1024 + d];
        float qv = g_qkv[b * NQKV + d];
        float nn = fv * n_in[b * Hdim + d] + iv * kv;
        out_n[b * Hdim + d] = nn;
        psum += qv * nn;
    }
    red[tid] = psum;
    __syncthreads();
#pragma unroll
    for (int s = 128; s > 0; s >>= 1) {
        if (tid < s) red[tid] += red[tid + s];
        __syncthreads();
    }
    if (tid == 0) g_denom[b] = fmaxf(red[0], 1e-6f);
}

// ---------------------------------------------------------------------------
// K3: streaming C update fused with h_lin reduction (single pass over C).
// grid = 128 b * 8 htiles = 1024 blocks, 256 threads (full 1024-wide d row).
// EXACT round-6 form (unroll 8).
// ---------------------------------------------------------------------------
#define TILE_H 128

__global__ __launch_bounds__(256) void update_C_kernel(
    const float* __restrict__ C, float* __restrict__ outC)
{
    const int bid = blockIdx.x;
    const int b  = bid >> 3;
    const int ht = bid & 7;
    const int tid = threadIdx.x;

    __shared__ float qs[TILE_H], fs[TILE_H], iks[TILE_H];
    if (tid < TILE_H) {
        int h = ht * TILE_H + tid;
        qs[tid]  = g_qkv[b * NQKV + h];
        float kv = g_qkv[b * NQKV + 1024 + h];
        float iv = g_ifo[b * NQKV + h];
        fs[tid]  = g_ifo[b * NQKV + 1024 + h];
        iks[tid] = iv * kv;
    }
    __syncthreads();

    const int d = tid * 4;
    const float4 v4 = *(const float4*)(g_qkv + b * NQKV + 2048 + d);

    const size_t base = (size_t)b * Hdim * Hdim + (size_t)ht * TILE_H * Hdim + d;
    const float* __restrict__ src = C + base;
    float* __restrict__ dst = outC + base;

    float4 acc = make_float4(0.f, 0.f, 0.f, 0.f);

#pragma unroll 8
    for (int j = 0; j < TILE_H; j++) {
        float4 c4 = __ldcs((const float4*)(src + (size_t)j * Hdim));
        const float fv = fs[j], ik = iks[j], qv = qs[j];
        float4 cn;
        cn.x = fmaf(fv, c4.x, ik * v4.x);
        cn.y = fmaf(fv, c4.y, ik * v4.y);
        cn.z = fmaf(fv, c4.z, ik * v4.z);
        cn.w = fmaf(fv, c4.w, ik * v4.w);
        __stcs((float4*)(dst + (size_t)j * Hdim), cn);
        acc.x = fmaf(qv, cn.x, acc.x);
        acc.y = fmaf(qv, cn.y, acc.y);
        acc.z = fmaf(qv, cn.z, acc.z);
        acc.w = fmaf(qv, cn.w, acc.w);
    }

    *(float4*)(g_hpart + ht * (Bsz * Hdim) + (b << 10) + d) = acc;
}

// ---------------------------------------------------------------------------
// K4: h_new = o * (sum_ht h_lin_part) / denom
// ---------------------------------------------------------------------------
__global__ __launch_bounds__(256) void finalize_h_kernel(float* __restrict__ out_h)
{
    const int idx = blockIdx.x * 256 + threadIdx.x;   // 131072 total
    const int b = idx >> 10;
    const int d = idx & 1023;
    float hl = 0.f;
#pragma unroll
    for (int p = 0; p < 8; p++) hl += g_hpart[p * (Bsz * Hdim) + (b << 10) + d];
    out_h[idx] = g_ifo[b * NQKV + 2048 + d] * hl / g_denom[b];
}

// ---------------------------------------------------------------------------
extern "C" void kernel_launch(void* const* d_in, const int* in_sizes, int n_in,
                              void* d_out, int out_size)
{
    // order-agnostic input resolution by element count
    const float *x = 0, *C = 0, *n_in_p = 0;
    const float *W_proj = 0, *b_proj = 0, *W_gates = 0, *b_gates = 0;

    const float* trio[3] = {0, 0, 0};
    int ntrio = 0;
    for (int idx = 0; idx < n_in; idx++) {
        const float* p = (const float*)d_in[idx];
        switch (in_sizes[idx]) {
            case 134217728: C       = p; break;
            case 4194304:   W_proj  = p; break;
            case 3145728:   W_gates = p; break;
            case 4096:      b_proj  = p; break;
            case 3072:      b_gates = p; break;
            case 131072:    if (ntrio < 3) trio[ntrio++] = p; break;
            default: break;
        }
    }
    n_in_p = trio[1];
    if (in_sizes[0] == 131072) x = trio[0];
    else                       x = trio[2];

    float* out   = (float*)d_out;
    float* out_h = out;
    float* out_C = out + Bsz * Hdim;
    float* out_n = out + Bsz * Hdim + (size_t)Bsz * Hdim * Hdim;

    dim3 ggrid(NQKV / 128, 1, KSPLIT);   // (24, 1, 6) = 144 blocks
    // K1: proj GEMM -> partials -> epi(tanh/identity) -> g_qkv
    gemm_main_kernel<0><<<ggrid, 256>>>(x, W_proj);
    gemm_epi_kernel<0><<<OUTMN / 256, 256>>>(b_proj);
    // K2: gates GEMM (A = v slice, resolved in-device) -> epi(sigmoid) -> g_ifo
    gemm_main_kernel<1><<<ggrid, 256>>>(nullptr, W_gates);
    gemm_epi_kernel<1><<<OUTMN / 256, 256>>>(b_gates);
    // n_new + denom
    nnew_denom_kernel<<<Bsz, 256>>>(n_in_p, out_n);
    // C update + fused h_lin reduction (single pass over C)
    update_C_kernel<<<Bsz * 8, 256>>>(C, out_C);
    // finalize h
    finalize_h_kernel<<<(Bsz * Hdim) / 256, 256>>>(out_h);
}